// round 4
// baseline (speedup 1.0000x reference)
#include <cuda_runtime.h>
#include <cstdint>
#include <math.h>

// Problem constants
#define BSZ   65536
#define KSZ   512
#define HSZ   128
#define NEXP  8      // 4 common + 4 task-specific (T*ES)
#define TT    2
#define ESP   2
#define ECM   4
#define ETOT  6

// 268 MB scratch for expert outputs: [expert][b][h]
// experts 0..3 = common, 4..7 = specific (t*ES + es)
__device__ float g_expert[(size_t)NEXP * BSZ * HSZ];

// ---------------------------------------------------------------------------
// tf32 helpers
// ---------------------------------------------------------------------------
__device__ __forceinline__ float to_tf32(float x) {
    uint32_t u;
    asm("cvt.rna.tf32.f32 %0, %1;" : "=r"(u) : "f"(x));
    return __uint_as_float(u);
}

__device__ __forceinline__ void mma_tf32(float* c, const uint32_t* a, const uint32_t* b) {
    asm volatile(
        "mma.sync.aligned.m16n8k8.row.col.f32.tf32.tf32.f32 "
        "{%0,%1,%2,%3}, {%4,%5,%6,%7}, {%8,%9}, {%0,%1,%2,%3};\n"
        : "+f"(c[0]), "+f"(c[1]), "+f"(c[2]), "+f"(c[3])
        : "r"(a[0]), "r"(a[1]), "r"(a[2]), "r"(a[3]),
          "r"(b[0]), "r"(b[1]));
}

// ---------------------------------------------------------------------------
// Kernel A: 8 expert GEMMs   out[e] = x @ W[e] + bias[e]
//   x: [B, K] row-major,  W[e]: [K, H] row-major
//   Block tile: BM=128, BN=128(=H), BK=32.  8 warps: 2(m) x 4(n), 64x32 each.
//   blockIdx.x = expert (inner -> 8 concurrent CTAs share x tile in L2)
//   blockIdx.y = m-tile
// ---------------------------------------------------------------------------
#define BM 128
#define BN 128
#define BK 32

__global__ void __launch_bounds__(256, 2)
expert_gemm_kernel(const float* __restrict__ x,
                   const float* __restrict__ Wc, const float* __restrict__ bc,
                   const float* __restrict__ Ws, const float* __restrict__ bs)
{
    const int e    = blockIdx.x;   // 0..7
    const int mblk = blockIdx.y;   // 0..511

    const float* W    = (e < ECM) ? (Wc + (size_t)e * KSZ * HSZ)
                                  : (Ws + (size_t)(e - ECM) * KSZ * HSZ);
    const float* bias = (e < ECM) ? (bc + e * HSZ)
                                  : (bs + (e - ECM) * HSZ);

    __shared__ __align__(16) float As[BM][BK + 4];   // stride 36 floats (144B, 16B-aligned rows)
    __shared__ __align__(16) float Bs[BK][BN + 4];   // stride 132 floats (528B, 16B-aligned rows)

    const int tid   = threadIdx.x;
    const int wid   = tid >> 5;
    const int lane  = tid & 31;
    const int group = lane >> 2;   // 0..7
    const int tig   = lane & 3;    // 0..3
    const int warp_m = (wid >> 2) * 64;   // 0 or 64
    const int warp_n = (wid & 3)  * 32;   // 0,32,64,96

    float acc[4][4][4];
    #pragma unroll
    for (int im = 0; im < 4; im++)
        #pragma unroll
        for (int in = 0; in < 4; in++)
            #pragma unroll
            for (int r = 0; r < 4; r++) acc[im][in][r] = 0.0f;

    const float* xblk = x + (size_t)mblk * BM * KSZ;

    for (int k0 = 0; k0 < KSZ; k0 += BK) {
        // load A tile: 128x32 floats = 1024 float4 over 256 threads
        #pragma unroll
        for (int i = 0; i < 4; i++) {
            int idx = tid + i * 256;
            int row = idx >> 3;           // 8 float4 per row
            int c   = (idx & 7) << 2;
            float4 v = *(const float4*)(xblk + (size_t)row * KSZ + k0 + c);
            v.x = to_tf32(v.x); v.y = to_tf32(v.y);
            v.z = to_tf32(v.z); v.w = to_tf32(v.w);
            *(float4*)&As[row][c] = v;
        }
        // load B tile: 32x128 floats = 1024 float4
        #pragma unroll
        for (int i = 0; i < 4; i++) {
            int idx = tid + i * 256;
            int row = idx >> 5;           // 32 float4 per row
            int c   = (idx & 31) << 2;
            float4 v = *(const float4*)(W + (size_t)(k0 + row) * HSZ + c);
            v.x = to_tf32(v.x); v.y = to_tf32(v.y);
            v.z = to_tf32(v.z); v.w = to_tf32(v.w);
            *(float4*)&Bs[row][c] = v;
        }
        __syncthreads();

        #pragma unroll
        for (int kk = 0; kk < BK; kk += 8) {
            uint32_t afr[4][4];
            #pragma unroll
            for (int im = 0; im < 4; im++) {
                int r = warp_m + im * 16 + group;
                afr[im][0] = __float_as_uint(As[r    ][kk + tig    ]);
                afr[im][1] = __float_as_uint(As[r + 8][kk + tig    ]);
                afr[im][2] = __float_as_uint(As[r    ][kk + tig + 4]);
                afr[im][3] = __float_as_uint(As[r + 8][kk + tig + 4]);
            }
            uint32_t bfr[4][2];
            #pragma unroll
            for (int in = 0; in < 4; in++) {
                int cn = warp_n + in * 8 + group;
                bfr[in][0] = __float_as_uint(Bs[kk + tig    ][cn]);
                bfr[in][1] = __float_as_uint(Bs[kk + tig + 4][cn]);
            }
            #pragma unroll
            for (int im = 0; im < 4; im++)
                #pragma unroll
                for (int in = 0; in < 4; in++)
                    mma_tf32(acc[im][in], afr[im], bfr[in]);
        }
        __syncthreads();
    }

    // epilogue: add bias, store fp32 scratch
    float* outp = g_expert + (size_t)e * BSZ * HSZ + (size_t)mblk * BM * HSZ;
    #pragma unroll
    for (int im = 0; im < 4; im++) {
        int r0 = warp_m + im * 16 + group;
        #pragma unroll
        for (int in = 0; in < 4; in++) {
            int cn = warp_n + in * 8 + tig * 2;
            float b0 = __ldg(&bias[cn]);
            float b1 = __ldg(&bias[cn + 1]);
            float2 v0 = make_float2(acc[im][in][0] + b0, acc[im][in][1] + b1);
            float2 v1 = make_float2(acc[im][in][2] + b0, acc[im][in][3] + b1);
            *(float2*)(outp + (size_t)r0      * HSZ + cn) = v0;
            *(float2*)(outp + (size_t)(r0+8)  * HSZ + cn) = v1;
        }
    }
}

// ---------------------------------------------------------------------------
// Kernel B: gating + softmax + weighted combine + final projection
//   out[t,b] = sum_e softmax_e( gate_in . Wg[t] + bg[t] ) * (tmp[t,e,b,:] . Wt[t]) + bt[t]
//   One warp per (t, b), 4 b's per warp. blockIdx.y = t.
// ---------------------------------------------------------------------------
#define BPW 4   // b's per warp

__global__ void __launch_bounds__(256)
gate_kernel(const float* __restrict__ Wg, const float* __restrict__ bg,
            const float* __restrict__ Wt, const float* __restrict__ bt,
            float* __restrict__ out)
{
    const int t = blockIdx.y;

    __shared__ __align__(16) float Wgt_s[ETOT][ETOT * HSZ];  // transposed: [oe][f]
    __shared__ __align__(16) float Wt_s[HSZ];
    __shared__ float bg_s[ETOT];
    __shared__ float bt_s;

    const int tid = threadIdx.x;
    for (int i = tid; i < ETOT * HSZ * ETOT; i += 256) {
        int f  = i / ETOT;
        int oe = i % ETOT;
        Wgt_s[oe][f] = Wg[(size_t)t * ETOT * HSZ * ETOT + i];
    }
    if (tid < HSZ)  Wt_s[tid] = Wt[t * HSZ + tid];
    if (tid < ETOT) bg_s[tid] = bg[t * ETOT + tid];
    if (tid == 0)   bt_s = bt[t];
    __syncthreads();

    const int wid  = tid >> 5;
    const int lane = tid & 31;
    const int b0   = (blockIdx.x * 8 + wid) * BPW;

    const float4 wt4 = *(const float4*)&Wt_s[4 * lane];

    for (int ib = 0; ib < BPW; ib++) {
        const int b = b0 + ib;

        // load this row's 6 expert vectors (order: spec0, spec1, common0..3)
        float4 v[ETOT];
        #pragma unroll
        for (int ep = 0; ep < ETOT; ep++) {
            int ge = (ep < ESP) ? (ECM + t * ESP + ep) : (ep - ESP);
            v[ep] = *(const float4*)(g_expert + (size_t)ge * BSZ * HSZ
                                              + (size_t)b * HSZ + 4 * lane);
        }

        float logit[ETOT], fe[ETOT];
        #pragma unroll
        for (int oe = 0; oe < ETOT; oe++) {
            float s = 0.0f;
            #pragma unroll
            for (int ep = 0; ep < ETOT; ep++) {
                const float4 w = *(const float4*)&Wgt_s[oe][ep * HSZ + 4 * lane];
                s += v[ep].x * w.x + v[ep].y * w.y + v[ep].z * w.z + v[ep].w * w.w;
            }
            logit[oe] = s;
        }
        #pragma unroll
        for (int ep = 0; ep < ETOT; ep++)
            fe[ep] = v[ep].x * wt4.x + v[ep].y * wt4.y + v[ep].z * wt4.z + v[ep].w * wt4.w;

        // butterfly-reduce all 12 values across the warp
        #pragma unroll
        for (int s = 16; s > 0; s >>= 1) {
            #pragma unroll
            for (int oe = 0; oe < ETOT; oe++) {
                logit[oe] += __shfl_xor_sync(0xFFFFFFFFu, logit[oe], s);
                fe[oe]    += __shfl_xor_sync(0xFFFFFFFFu, fe[oe], s);
            }
        }

        if (lane == 0) {
            float m = -1e30f;
            #pragma unroll
            for (int oe = 0; oe < ETOT; oe++) {
                logit[oe] += bg_s[oe];
                m = fmaxf(m, logit[oe]);
            }
            float den = 0.0f, num = 0.0f;
            #pragma unroll
            for (int oe = 0; oe < ETOT; oe++) {
                float w = __expf(logit[oe] - m);
                den += w;
                num += w * fe[oe];
            }
            out[(size_t)t * BSZ + b] = num / den + bt_s;
        }
    }
}

// ---------------------------------------------------------------------------
// Launch
// ---------------------------------------------------------------------------
extern "C" void kernel_launch(void* const* d_in, const int* in_sizes, int n_in,
                              void* d_out, int out_size)
{
    (void)in_sizes; (void)n_in; (void)out_size;
    const float* x  = (const float*)d_in[0];
    const float* Wc = (const float*)d_in[1];
    const float* bc = (const float*)d_in[2];
    const float* Ws = (const float*)d_in[3];
    const float* bs = (const float*)d_in[4];
    const float* Wg = (const float*)d_in[5];
    const float* bg = (const float*)d_in[6];
    const float* Wt = (const float*)d_in[7];
    const float* bt = (const float*)d_in[8];
    float* out = (float*)d_out;

    dim3 gridA(NEXP, BSZ / BM);              // expert fastest -> x tiles shared in L2
    expert_gemm_kernel<<<gridA, 256>>>(x, Wc, bc, Ws, bs);

    dim3 gridB(BSZ / (8 * BPW), TT);
    gate_kernel<<<gridB, 256>>>(Wg, bg, Wt, bt, out);
}

// round 7
// speedup vs baseline: 3.1082x; 3.1082x over previous
#include <cuda_runtime.h>
#include <cstdint>

// Problem constants
#define BSZ   65536
#define ISZ   512
#define HSZ   128
#define TT    2
#define ESP   2
#define ECM   4
#define ETOT  6

// Fused matrices: C[48][512]  (row c = t*24 + cc; cc 0..5 = logit col, 6..11 = fe col)
// Db[48]: per-column bias (logit: b-part + bg;  fe: b_e . Wt)
__device__ __align__(16) float g_C[48 * ISZ];
__device__ float g_Db[48];

// ---------------------------------------------------------------------------
// helpers
// ---------------------------------------------------------------------------
__device__ __forceinline__ uint32_t smem_u32(const void* p) {
    uint32_t a;
    asm("{ .reg .u64 t; cvta.to.shared.u64 t, %1; cvt.u32.u64 %0, t; }"
        : "=r"(a) : "l"(p));
    return a;
}

#define CP_ASYNC16(sm, g) \
    asm volatile("cp.async.cg.shared.global [%0], [%1], 16;" :: "r"(sm), "l"(g))
#define CP_COMMIT() asm volatile("cp.async.commit_group;" ::: "memory")
#define CP_WAIT1()  asm volatile("cp.async.wait_group 1;" ::: "memory")
#define CP_WAIT0()  asm volatile("cp.async.wait_group 0;" ::: "memory")

__device__ __forceinline__ const float* wsel(const float* Wc, const float* Ws,
                                             int t, int ep) {
    return (ep < ESP) ? (Ws + (size_t)(t * ESP + ep) * ISZ * HSZ)
                      : (Wc + (size_t)(ep - ESP) * ISZ * HSZ);
}
__device__ __forceinline__ const float* bselp(const float* bc, const float* bs,
                                              int t, int ep) {
    return (ep < ESP) ? (bs + (t * ESP + ep) * HSZ) : (bc + (ep - ESP) * HSZ);
}

// ---------------------------------------------------------------------------
// Kernel 1: precompute fused matrices.
//   One warp per output element. Jobs:
//     [0, 24576): C[c][i]   (c = wg>>9, i = wg&511)
//     [24576, 24624): Db[c]
// ---------------------------------------------------------------------------
__global__ void __launch_bounds__(256)
precompute_kernel(const float* __restrict__ Wc, const float* __restrict__ bc,
                  const float* __restrict__ Ws, const float* __restrict__ bs,
                  const float* __restrict__ Wg, const float* __restrict__ bg,
                  const float* __restrict__ Wt)
{
    const int lane = threadIdx.x & 31;
    const int wg   = blockIdx.x * 8 + (threadIdx.x >> 5);

    float s = 0.0f;
    if (wg < 48 * ISZ) {
        const int c  = wg >> 9;
        const int i  = wg & 511;
        const int t  = c / 24;
        const int cc = c % 24;
        if (cc < ETOT) {
            // logit column: sum over 6 experts x 128 h
            #pragma unroll
            for (int ep = 0; ep < ETOT; ep++) {
                const float* W = wsel(Wc, Ws, t, ep);
                #pragma unroll
                for (int h = lane; h < HSZ; h += 32)
                    s += W[(size_t)i * HSZ + h]
                       * Wg[(size_t)t * (ETOT * HSZ * ETOT) + (ep * HSZ + h) * ETOT + cc];
            }
        } else {
            const int e = cc - ETOT;
            const float* W = wsel(Wc, Ws, t, e);
            #pragma unroll
            for (int h = lane; h < HSZ; h += 32)
                s += W[(size_t)i * HSZ + h] * Wt[t * HSZ + h];
        }
        #pragma unroll
        for (int o = 16; o > 0; o >>= 1) s += __shfl_xor_sync(0xFFFFFFFFu, s, o);
        if (lane == 0) g_C[(size_t)c * ISZ + i] = s;
    } else if (wg < 48 * ISZ + 48) {
        const int c  = wg - 48 * ISZ;
        const int t  = c / 24;
        const int cc = c % 24;
        if (cc < ETOT) {
            for (int f = lane; f < ETOT * HSZ; f += 32) {
                const int ep = f >> 7, h = f & 127;
                s += bselp(bc, bs, t, ep)[h]
                   * Wg[(size_t)t * (ETOT * HSZ * ETOT) + f * ETOT + cc];
            }
        } else {
            const int e = cc - ETOT;
            for (int h = lane; h < HSZ; h += 32)
                s += bselp(bc, bs, t, e)[h] * Wt[t * HSZ + h];
        }
        #pragma unroll
        for (int o = 16; o > 0; o >>= 1) s += __shfl_xor_sync(0xFFFFFFFFu, s, o);
        if (lane == 0) {
            if (cc < ETOT) s += bg[t * ETOT + cc];
            g_Db[c] = s;
        }
    }
}

// ---------------------------------------------------------------------------
// Kernel 2: main pass.  out[t,b] = softmax(logits).fe + bt[t]
//   Grid 1024 CTAs x 256 thr, 4 tiles of 16 rows per CTA.
//   SMEM: C [48][512] f32 @ 0 (98304 B)
//         x tiles [2][16][512] @ 98304 (2 x 32768)
//         Db[48] @ 163840,  bt[2] @ 164032
// ---------------------------------------------------------------------------
#define RTILE     16
#define NT_PER    4
#define OFF_X     98304
#define OFF_DB    163840
#define OFF_BT    164032
#define SMEM_MAIN 164096

__device__ __forceinline__ void load_xtile(uint32_t dst, const float* x,
                                           int row0, int tid)
{
    // 16 rows x 512 floats = 2048 float4; 8 per thread
    #pragma unroll
    for (int k = 0; k < 8; k++) {
        const int idx = tid + k * 256;
        const int r   = idx >> 7;        // 128 float4 per row
        const int c4  = idx & 127;
        CP_ASYNC16(dst + (uint32_t)idx * 16,
                   x + (size_t)(row0 + r) * ISZ + c4 * 4);
    }
}

__global__ void __launch_bounds__(256, 1)
main_kernel(const float* __restrict__ x, const float* __restrict__ bt,
            float* __restrict__ out)
{
    extern __shared__ __align__(16) char smem[];
    const uint32_t sb = smem_u32(smem);
    const int tid  = threadIdx.x;
    const int wid  = tid >> 5;
    const int lane = tid & 31;

    float4* Cs = (float4*)smem;                      // [48*128] float4

    // stage C (L2-resident after first CTA wave)
    {
        const float4* Cg = (const float4*)g_C;
        #pragma unroll
        for (int k = 0; k < 24; k++)
            Cs[tid + k * 256] = Cg[tid + k * 256];
        if (tid < 48) ((float*)(smem + OFF_DB))[tid] = g_Db[tid];
        if (tid < TT) ((float*)(smem + OFF_BT))[tid] = bt[tid];
    }

    const int tile0 = blockIdx.x * NT_PER;
    load_xtile(sb + OFF_X, x, tile0 * RTILE, tid);
    CP_COMMIT();

    const float* Dbs = (const float*)(smem + OFF_DB);
    const float* bts = (const float*)(smem + OFF_BT);

    for (int it = 0; it < NT_PER; it++) {
        const int buf = it & 1;
        __syncthreads();                 // prev compute done: other buffer free
        if (it + 1 < NT_PER) {
            load_xtile(sb + OFF_X + (buf ^ 1) * 32768, x,
                       (tile0 + it + 1) * RTILE, tid);
            CP_COMMIT();
            CP_WAIT1();
        } else {
            CP_WAIT0();
        }
        __syncthreads();                 // tile it visible to all threads

        const float4* xs = (const float4*)(smem + OFF_X + buf * 32768);

        #pragma unroll
        for (int rr = 0; rr < 2; rr++) {
            const int r = wid * 2 + rr;
            const int b = (tile0 + it) * RTILE + r;

            float p[48];
            #pragma unroll
            for (int c = 0; c < 48; c++) p[c] = 0.0f;

            #pragma unroll
            for (int j = 0; j < 4; j++) {
                const float4 xv = xs[r * 128 + j * 32 + lane];
                #pragma unroll
                for (int c = 0; c < 48; c++) {
                    const float4 cv = Cs[c * 128 + j * 32 + lane];
                    p[c] += xv.x * cv.x + xv.y * cv.y + xv.z * cv.z + xv.w * cv.w;
                }
            }
            #pragma unroll
            for (int o = 16; o > 0; o >>= 1) {
                #pragma unroll
                for (int c = 0; c < 48; c++)
                    p[c] += __shfl_xor_sync(0xFFFFFFFFu, p[c], o);
            }

            if (lane == 0) {
                #pragma unroll
                for (int t = 0; t < TT; t++) {
                    const int base = t * 24;
                    float lg[ETOT], m = -1e30f;
                    #pragma unroll
                    for (int oe = 0; oe < ETOT; oe++) {
                        lg[oe] = p[base + oe] + Dbs[base + oe];
                        m = fmaxf(m, lg[oe]);
                    }
                    float den = 0.0f, num = 0.0f;
                    #pragma unroll
                    for (int oe = 0; oe < ETOT; oe++) {
                        const float w = __expf(lg[oe] - m);
                        den += w;
                        num += w * (p[base + ETOT + oe] + Dbs[base + ETOT + oe]);
                    }
                    out[(size_t)t * BSZ + b] = num / den + bts[t];
                }
            }
        }
    }
}

// ---------------------------------------------------------------------------
// Launch
// ---------------------------------------------------------------------------
extern "C" void kernel_launch(void* const* d_in, const int* in_sizes, int n_in,
                              void* d_out, int out_size)
{
    (void)in_sizes; (void)n_in; (void)out_size;
    const float* x  = (const float*)d_in[0];
    const float* Wc = (const float*)d_in[1];
    const float* bc = (const float*)d_in[2];
    const float* Ws = (const float*)d_in[3];
    const float* bs = (const float*)d_in[4];
    const float* Wg = (const float*)d_in[5];
    const float* bg = (const float*)d_in[6];
    const float* Wt = (const float*)d_in[7];
    const float* bt = (const float*)d_in[8];
    float* out = (float*)d_out;

    cudaFuncSetAttribute(main_kernel,
                         cudaFuncAttributeMaxDynamicSharedMemorySize, SMEM_MAIN);

    const int njobs = 48 * ISZ + 48;
    precompute_kernel<<<(njobs + 7) / 8, 256>>>(Wc, bc, Ws, bs, Wg, bg, Wt);

    main_kernel<<<BSZ / (RTILE * NT_PER), 256, SMEM_MAIN>>>(x, bt, out);
}

// round 12
// speedup vs baseline: 8.7690x; 2.8212x over previous
#include <cuda_runtime.h>
#include <cstdint>

// Problem constants
#define BSZ   65536
#define ISZ   512
#define HSZ   128
#define TT    2
#define ESP   2
#define ECM   4
#define ETOT  6

// Fused matrix: C[24][512].  Row c = t*12 + cc; cc 0..5 = logit cols, 6..11 = fe cols.
// Db[24]: per-column bias (logit: bias-part + bg ; fe: b_e . Wt)
#define NC 24
__device__ __align__(16) float g_C[NC * ISZ];
__device__ float g_Db[NC];

// ---------------------------------------------------------------------------
// helpers
// ---------------------------------------------------------------------------
__device__ __forceinline__ uint32_t smem_u32(const void* p) {
    uint32_t a;
    asm("{ .reg .u64 t; cvta.to.shared.u64 t, %1; cvt.u32.u64 %0, t; }"
        : "=r"(a) : "l"(p));
    return a;
}

#define CP_ASYNC16(sm, g) \
    asm volatile("cp.async.cg.shared.global [%0], [%1], 16;" :: "r"(sm), "l"(g))
#define CP_COMMIT() asm volatile("cp.async.commit_group;" ::: "memory")
#define CP_WAIT1()  asm volatile("cp.async.wait_group 1;" ::: "memory")
#define CP_WAIT0()  asm volatile("cp.async.wait_group 0;" ::: "memory")

// packed fp32x2 FMA (Blackwell): d = a*b + d, elementwise on 2 packed floats
#define FMA2(d, a, b) \
    asm("fma.rn.f32x2 %0, %1, %2, %0;" : "+l"(d) : "l"(a), "l"(b))

__device__ __forceinline__ const float* wsel(const float* Wc, const float* Ws,
                                             int t, int ep) {
    return (ep < ESP) ? (Ws + (size_t)(t * ESP + ep) * ISZ * HSZ)
                      : (Wc + (size_t)(ep - ESP) * ISZ * HSZ);
}
__device__ __forceinline__ const float* bselp(const float* bc, const float* bs,
                                              int t, int ep) {
    return (ep < ESP) ? (bs + (t * ESP + ep) * HSZ) : (bc + (ep - ESP) * HSZ);
}

// ---------------------------------------------------------------------------
// Kernel 1: precompute fused matrix (warp per element).
//   jobs [0, 24*512): C[c][i]     c = job>>9, i = job&511
//   jobs [24*512, 24*512+24): Db[c]
// ---------------------------------------------------------------------------
__global__ void __launch_bounds__(256)
precompute_kernel(const float* __restrict__ Wc, const float* __restrict__ bc,
                  const float* __restrict__ Ws, const float* __restrict__ bs,
                  const float* __restrict__ Wg, const float* __restrict__ bg,
                  const float* __restrict__ Wt)
{
    const int lane = threadIdx.x & 31;
    const int wg   = blockIdx.x * 8 + (threadIdx.x >> 5);

    float s = 0.0f;
    if (wg < NC * ISZ) {
        const int c  = wg >> 9;
        const int i  = wg & 511;
        const int t  = c / 12;
        const int cc = c % 12;
        if (cc < ETOT) {
            #pragma unroll
            for (int ep = 0; ep < ETOT; ep++) {
                const float* W = wsel(Wc, Ws, t, ep);
                #pragma unroll
                for (int h = lane; h < HSZ; h += 32)
                    s += W[(size_t)i * HSZ + h]
                       * Wg[(size_t)t * (ETOT * HSZ * ETOT) + (ep * HSZ + h) * ETOT + cc];
            }
        } else {
            const int e = cc - ETOT;                 // 0..5
            const float* W = wsel(Wc, Ws, t, e);
            #pragma unroll
            for (int h = lane; h < HSZ; h += 32)
                s += W[(size_t)i * HSZ + h] * Wt[t * HSZ + h];
        }
        #pragma unroll
        for (int o = 16; o > 0; o >>= 1) s += __shfl_xor_sync(0xFFFFFFFFu, s, o);
        if (lane == 0) g_C[(size_t)c * ISZ + i] = s;
    } else if (wg < NC * ISZ + NC) {
        const int c  = wg - NC * ISZ;
        const int t  = c / 12;
        const int cc = c % 12;
        if (cc < ETOT) {
            for (int f = lane; f < ETOT * HSZ; f += 32) {
                const int ep = f >> 7, h = f & 127;
                s += bselp(bc, bs, t, ep)[h]
                   * Wg[(size_t)t * (ETOT * HSZ * ETOT) + f * ETOT + cc];
            }
        } else {
            const int e = cc - ETOT;
            for (int h = lane; h < HSZ; h += 32)
                s += bselp(bc, bs, t, e)[h] * Wt[t * HSZ + h];
        }
        #pragma unroll
        for (int o = 16; o > 0; o >>= 1) s += __shfl_xor_sync(0xFFFFFFFFu, s, o);
        if (lane == 0) {
            if (cc < ETOT) s += bg[t * ETOT + cc];
            g_Db[c] = s;
        }
    }
}

// ---------------------------------------------------------------------------
// Kernel 2: main pass — thread per row.
//   p[c] = x[b] . C[c]  (24 dots of 512), then per-thread softmax/combine.
//   x staged in smem: 32 chunks of 16 k, double-buffered cp.async.
// SMEM: C [24][512] f32  @ 0        (49152 B)
//       x [2][256 rows][20 floats] @ 49152  (2 x 20480 B; stride 20 = 16B-aligned rows)
// ---------------------------------------------------------------------------
#define KCH      16
#define NCHUNK   (ISZ / KCH)          // 32
#define XSTRIDE  20                   // floats per staged row (pad 16 -> 20)
#define XBUF     (256 * XSTRIDE * 4)  // 20480 B
#define OFF_X    (NC * ISZ * 4)       // 49152
#define SMEM_MAIN (OFF_X + 2 * XBUF)  // 90112

__device__ __forceinline__ void load_chunk(uint32_t xb, const float* x,
                                           int row0, int kc, int tid)
{
    // 256 rows x 16 floats = 1024 x 16B ops, 4 per thread
    #pragma unroll
    for (int k = 0; k < 4; k++) {
        const int idx = tid + k * 256;
        const int r   = idx >> 2;
        const int q   = idx & 3;
        CP_ASYNC16(xb + (uint32_t)(r * XSTRIDE + q * 4) * 4,
                   x + (size_t)(row0 + r) * ISZ + kc * KCH + q * 4);
    }
}

__global__ void __launch_bounds__(256, 2)
main_kernel(const float* __restrict__ x, const float* __restrict__ bt,
            float* __restrict__ out)
{
    extern __shared__ __align__(16) char smem[];
    const uint32_t sb  = smem_u32(smem);
    const int tid  = threadIdx.x;
    const int row0 = blockIdx.x * 256;
    const int b    = row0 + tid;

    // stage C (48 KB) + chunk 0 in one cp.async group
    {
        const float4* Cg = (const float4*)g_C;
        #pragma unroll
        for (int k = 0; k < 12; k++) {
            const int idx = tid + k * 256;
            CP_ASYNC16(sb + (uint32_t)idx * 16, Cg + idx);
        }
    }
    load_chunk(sb + OFF_X, x, row0, 0, tid);
    CP_COMMIT();

    uint64_t acc[NC];
    #pragma unroll
    for (int c = 0; c < NC; c++) acc[c] = 0ull;

    for (int kc = 0; kc < NCHUNK; kc++) {
        const int buf = kc & 1;
        if (kc + 1 < NCHUNK) {
            load_chunk(sb + OFF_X + (buf ^ 1) * XBUF, x, row0, kc + 1, tid);
            CP_COMMIT();
            CP_WAIT1();
        } else {
            CP_WAIT0();
        }
        __syncthreads();     // chunk kc visible

        // this thread's 16 x-values (8 packed pairs)
        const uint64_t* xr =
            (const uint64_t*)(smem + OFF_X + buf * XBUF + tid * (XSTRIDE * 4));
        uint64_t xv[8];
        #pragma unroll
        for (int j = 0; j < 8; j++) xv[j] = xr[j];

        #pragma unroll
        for (int c = 0; c < NC; c++) {
            const ulonglong2* cp =
                (const ulonglong2*)(smem + (size_t)(c * ISZ + kc * KCH) * 4);
            ulonglong2 q0 = cp[0], q1 = cp[1], q2 = cp[2], q3 = cp[3];
            FMA2(acc[c], xv[0], q0.x); FMA2(acc[c], xv[1], q0.y);
            FMA2(acc[c], xv[2], q1.x); FMA2(acc[c], xv[3], q1.y);
            FMA2(acc[c], xv[4], q2.x); FMA2(acc[c], xv[5], q2.y);
            FMA2(acc[c], xv[6], q3.x); FMA2(acc[c], xv[7], q3.y);
        }
        __syncthreads();     // all threads done with buf before it is reloaded
    }

    // tail: fold pairs, add bias, per-thread softmax + combine
    float p[NC];
    #pragma unroll
    for (int c = 0; c < NC; c++) {
        const float lo = __uint_as_float((uint32_t)acc[c]);
        const float hi = __uint_as_float((uint32_t)(acc[c] >> 32));
        p[c] = lo + hi + __ldg(&g_Db[c]);
    }

    #pragma unroll
    for (int t = 0; t < TT; t++) {
        const int base = t * 12;
        float m = -1e30f;
        #pragma unroll
        for (int oe = 0; oe < ETOT; oe++) m = fmaxf(m, p[base + oe]);
        float den = 0.0f, num = 0.0f;
        #pragma unroll
        for (int oe = 0; oe < ETOT; oe++) {
            const float w = __expf(p[base + oe] - m);
            den += w;
            num += w * p[base + ETOT + oe];
        }
        out[(size_t)t * BSZ + b] = num / den + __ldg(&bt[t]);
    }
}

// ---------------------------------------------------------------------------
// Launch
// ---------------------------------------------------------------------------
extern "C" void kernel_launch(void* const* d_in, const int* in_sizes, int n_in,
                              void* d_out, int out_size)
{
    (void)in_sizes; (void)n_in; (void)out_size;
    const float* x  = (const float*)d_in[0];
    const float* Wc = (const float*)d_in[1];
    const float* bc = (const float*)d_in[2];
    const float* Ws = (const float*)d_in[3];
    const float* bs = (const float*)d_in[4];
    const float* Wg = (const float*)d_in[5];
    const float* bg = (const float*)d_in[6];
    const float* Wt = (const float*)d_in[7];
    const float* bt = (const float*)d_in[8];
    float* out = (float*)d_out;

    cudaFuncSetAttribute(main_kernel,
                         cudaFuncAttributeMaxDynamicSharedMemorySize, SMEM_MAIN);

    const int njobs = NC * ISZ + NC;                  // 12312 warp-jobs
    precompute_kernel<<<(njobs + 7) / 8, 256>>>(Wc, bc, Ws, bs, Wg, bg, Wt);

    main_kernel<<<BSZ / 256, 256, SMEM_MAIN>>>(x, bt, out);
}